// round 10
// baseline (speedup 1.0000x reference)
#include <cuda_runtime.h>

#define B_   8
#define S_   32
#define D_   256
#define M_   2048
#define GPB  16      // blocks per batch (slices of M)
#define RPB  128     // rows per slice
#define NT   256     // threads per block
#define PST  272     // floats per partial record
#define NBLK 64      // 16 slices x 4 batch-pairs; each block serves 2 batches
#define NEGINF (__int_as_float(0xff800000))

// ----------------------------- device state -----------------------------
__device__ float g_mem [B_*M_*D_];        // per-batch working rows (filled from regs at t=0)
__device__ float g_qt  [B_*S_*D_];        // (x@Wq+bq)@Wk^T / sqrt(D)
__device__ float g_xg  [B_*S_*D_];        // x@Wg1 + bg
__device__ float g_bgc [D_];              // bv@Wg2
__device__ float g_C   [D_*D_];           // Wv@Wg2
__device__ float g_part[2*B_*GPB*PST];    // partials, double buffered by step parity
__device__ int   g_tidx[2*B_*GPB*8];      // top8 global row ids
__device__ float g_gv  [B_*D_];           // gate vector per batch
__device__ int   g_cnt [2*B_*S_];         // cA[256] then cB[256], zeroed by init

__device__ __forceinline__ int ldacq(const int* p) {
    int v;
    asm volatile("ld.acquire.gpu.global.b32 %0, [%1];" : "=r"(v) : "l"(p) : "memory");
    return v;
}
// release-arrive without the L1D-flushing CCTL.IVALL of __threadfence()
__device__ __forceinline__ void red_release(int* p) {
    asm volatile("red.release.gpu.global.add.s32 [%0], %1;" :: "l"(p), "r"(1) : "memory");
}

// ----------------------------- init kernel (97 blocks) -----------------------------
__global__ void __launch_bounds__(NT)
mal_init(const float* __restrict__ x,  const float* __restrict__ Wq,
         const float* __restrict__ bq, const float* __restrict__ Wk,
         const float* __restrict__ Wv, const float* __restrict__ bv,
         const float* __restrict__ Wg, const float* __restrict__ bg)
{
    __shared__ float s_buf[2048];
    const int bid = blockIdx.x, tid = threadIdx.x;
    const int lane = tid & 31, warp = tid >> 5;

    if (bid == 96) {
        for (int i = tid; i < 2*B_*S_; i += NT) g_cnt[i] = 0;
        float acc = 0.f;
        #pragma unroll 16
        for (int j = 0; j < D_; ++j) acc += bv[j] * Wg[(D_ + j)*D_ + tid];
        g_bgc[tid] = acc;
        return;
    }
    const int which = bid >> 5;               // 0: qt-chain, 1: xg, 2: C
    const int sub   = bid & 31;
    const int r0    = sub * 8;
    const float* srcA = (which == 2) ? (Wv + r0*D_) : (x + r0*D_);
    for (int i = tid; i < 2048; i += NT) s_buf[i] = srcA[i];
    __syncthreads();
    const float* Wcol = (which == 0) ? Wq : (which == 1 ? Wg : (Wg + D_*D_));
    float acc[8];
    #pragma unroll
    for (int r = 0; r < 8; ++r) acc[r] = 0.f;
    #pragma unroll 16
    for (int j = 0; j < D_; ++j) {
        float w = Wcol[j*D_ + tid];
        #pragma unroll
        for (int r = 0; r < 8; ++r) acc[r] += s_buf[r*D_ + j] * w;
    }
    if (which == 1) {
        float bb = bg[tid];
        #pragma unroll
        for (int r = 0; r < 8; ++r) g_xg[(r0+r)*D_ + tid] = acc[r] + bb;
    } else if (which == 2) {
        #pragma unroll
        for (int r = 0; r < 8; ++r) g_C[(r0+r)*D_ + tid] = acc[r];
    } else {
        float bb = bq[tid];
        __syncthreads();
        #pragma unroll
        for (int r = 0; r < 8; ++r) s_buf[r*D_ + tid] = acc[r] + bb;
        __syncthreads();
        float4 t0[8], t1[8];
        #pragma unroll
        for (int r = 0; r < 8; ++r) {
            t0[r] = *(const float4*)(s_buf + r*D_ + lane*4);
            t1[r] = *(const float4*)(s_buf + r*D_ + 128 + lane*4);
        }
        int d = warp * 32;
        float4 w0 = *(const float4*)(Wk + d*D_ + lane*4);
        float4 w1 = *(const float4*)(Wk + d*D_ + 128 + lane*4);
        for (int dd = 0; dd < 32; ++dd) {
            float4 c0 = w0, c1 = w1;
            if (dd < 31) {
                w0 = *(const float4*)(Wk + (d+1)*D_ + lane*4);
                w1 = *(const float4*)(Wk + (d+1)*D_ + 128 + lane*4);
            }
            float dt[8];
            #pragma unroll
            for (int r = 0; r < 8; ++r) {
                dt[r] = t0[r].x*c0.x + t0[r].y*c0.y + t0[r].z*c0.z + t0[r].w*c0.w
                      + t1[r].x*c1.x + t1[r].y*c1.y + t1[r].z*c1.z + t1[r].w*c1.w;
                #pragma unroll
                for (int o = 16; o; o >>= 1) dt[r] += __shfl_xor_sync(0xffffffffu, dt[r], o);
            }
            if (lane == 0) {
                #pragma unroll
                for (int r = 0; r < 8; ++r) g_qt[(r0+r)*D_ + d] = dt[r] * 0.0625f;
            }
            ++d;
        }
    }
}

// ----------------------------- main persistent kernel -----------------------------
// Each block serves batch pair {b0, b0+4} for slice blk. The two independent
// timelines interleave so one batch's inter-block latency chain (store ->
// release -> poll -> merge reads -> gate handoff) hides behind the other's work.
__global__ void __launch_bounds__(NT, 1)
mal_main(const float* __restrict__ x, const float* __restrict__ memory,
         const float* __restrict__ Wv, const float* __restrict__ bv,
         float* __restrict__ out)
{
    __shared__ float s_wacc[2][8][D_];
    __shared__ float s_wm[2][8], s_ws[2][8];
    __shared__ float s_lg[2][128];
    __shared__ unsigned long long s_pk[2][128];
    __shared__ int   s_ci[2][128];
    __shared__ int   s_sel[2][8];
    __shared__ float s_p[2][D_];
    __shared__ float s_red[2][128];

    const int tid  = threadIdx.x, lane = tid & 31, warp = tid >> 5;
    const int bid  = blockIdx.x;
    const int blk  = bid & 15;
    const int bsA[2] = { bid >> 4, (bid >> 4) + 4 };
    const int d0   = lane * 4;
    const int d1   = 128 + lane * 4;
    const int dbase = blk * 16;
    const float* bMem = memory + (blk*RPB + warp*16) * D_;   // t=0 source (batch-shared)

    for (int t = 0; t < S_; ++t) {
        const int buf  = t & 1;
        float* partB = g_part + buf*(B_*GPB*PST);
        int*   tidxB = g_tidx + buf*(B_*GPB*8);

        // ---- owner updates for both batches ----
        if (t > 0) {
            #pragma unroll
            for (int pb = 0; pb < 2; ++pb) {
                const int b = bsA[pb];
                bool own = false;
                #pragma unroll
                for (int k = 0; k < 8; ++k) own |= ((s_sel[pb][k] >> 7) == blk);
                if (own) {
                    if (tid == 0) { while (ldacq(&g_cnt[B_*S_ + b*S_ + t-1]) < GPB) { } }
                    __syncthreads();
                    float gd   = __ldcg(&g_gv[b*D_ + tid]);
                    float xd   = __ldg(&x[(b*S_ + (t-1))*D_ + tid]);
                    float keep = 1.0f - gd, add = gd * xd;
                    #pragma unroll
                    for (int k = 0; k < 8; ++k) {
                        int gi = s_sel[pb][k];
                        if ((gi >> 7) == blk) {
                            float* row = g_mem + (b*M_ + gi)*D_;
                            row[tid] = keep * row[tid] + add;
                        }
                    }
                    __syncthreads();
                }
            }
        }

        // ---- phase A for both batches (independent; back-to-back) ----
        #pragma unroll
        for (int pb = 0; pb < 2; ++pb) {
            const int b = bsA[pb];
            const float4 qa = *(const float4*)(g_qt + (b*S_ + t)*D_ + d0);
            const float4 qb = *(const float4*)(g_qt + (b*S_ + t)*D_ + d1);
            float* gRow = g_mem + (b*M_ + blk*RPB + warp*16) * D_;
            const float* rowp = (t == 0) ? bMem : gRow;
            float4 ra[16], rb[16];
            float dts[16];
            float mw = NEGINF;
            #pragma unroll
            for (int r = 0; r < 16; ++r) {
                ra[r] = *(const float4*)(rowp + r*D_ + d0);
                rb[r] = *(const float4*)(rowp + r*D_ + d1);
                float dt = ra[r].x*qa.x + ra[r].y*qa.y + ra[r].z*qa.z + ra[r].w*qa.w
                         + rb[r].x*qb.x + rb[r].y*qb.y + rb[r].z*qb.z + rb[r].w*qb.w;
                #pragma unroll
                for (int o = 16; o; o >>= 1) dt += __shfl_xor_sync(0xffffffffu, dt, o);
                dts[r] = dt;
                mw = fmaxf(mw, dt);
                if (lane == 0) s_lg[pb][warp*16 + r] = dt;
            }
            if (t == 0) {
                #pragma unroll
                for (int r = 0; r < 16; ++r) {
                    *(float4*)(gRow + r*D_ + d0) = ra[r];
                    *(float4*)(gRow + r*D_ + d1) = rb[r];
                }
            }
            float sw = 0.f;
            float4 A = {0,0,0,0}, Bb = {0,0,0,0};
            #pragma unroll
            for (int r = 0; r < 16; ++r) {
                float e = __expf(dts[r] - mw);
                sw += e;
                A.x += e*ra[r].x; A.y += e*ra[r].y; A.z += e*ra[r].z; A.w += e*ra[r].w;
                Bb.x += e*rb[r].x; Bb.y += e*rb[r].y; Bb.z += e*rb[r].z; Bb.w += e*rb[r].w;
            }
            *(float4*)&s_wacc[pb][warp][d0] = A;
            *(float4*)&s_wacc[pb][warp][d1] = Bb;
            if (lane == 0) { s_wm[pb][warp] = mw; s_ws[pb][warp] = sw; }
        }
        __syncthreads();                                            // S1

        // ---- stage 2 for both batches ----
        #pragma unroll
        for (int pb = 0; pb < 2; ++pb) {
            const int b = bsA[pb];
            float* part = partB + (b*GPB + blk)*PST;
            float m0 = fmaxf(fmaxf(s_wm[pb][0], s_wm[pb][1]), fmaxf(s_wm[pb][2], s_wm[pb][3]));
            float m1 = fmaxf(fmaxf(s_wm[pb][4], s_wm[pb][5]), fmaxf(s_wm[pb][6], s_wm[pb][7]));
            float bm = fmaxf(m0, m1);
            float sc[8];
            #pragma unroll
            for (int w = 0; w < 8; ++w) sc[w] = __expf(s_wm[pb][w] - bm);
            float pv = 0.f;
            #pragma unroll
            for (int w = 0; w < 8; ++w) pv += s_wacc[pb][w][tid] * sc[w];
            part[2 + tid] = pv;
            if (tid == 0) {
                float sw = 0.f;
                #pragma unroll
                for (int w = 0; w < 8; ++w) sw += s_ws[pb][w] * sc[w];
                part[0] = bm; part[1] = sw;
            }
            if (tid < 128) {
                unsigned fb = __float_as_uint(s_lg[pb][tid]);
                fb ^= (fb & 0x80000000u) ? 0xFFFFFFFFu : 0x80000000u;
                s_pk[pb][tid] = ((unsigned long long)fb << 32) | (unsigned)(~tid);
            }
        }
        __syncthreads();                                            // S2

        // ---- local top-8 rank: warps 0-3 -> pb0, warps 4-7 -> pb1 ----
        {
            const int pb = tid >> 7, c = tid & 127;
            const int b = bsA[pb];
            unsigned long long me = s_pk[pb][c];
            int rk = 0;
            #pragma unroll 16
            for (int j = 0; j < 128; ++j) rk += (s_pk[pb][j] > me);
            if (rk < 8) {
                partB[(b*GPB + blk)*PST + 258 + rk] = s_lg[pb][c];
                tidxB[(b*GPB + blk)*8 + rk] = blk*RPB + c;
            }
        }
        __syncthreads();                                            // S3
        // ---- global barrier A for both batches ----
        if (tid == 0) {
            red_release(&g_cnt[bsA[0]*S_ + t]);
            red_release(&g_cnt[bsA[1]*S_ + t]);
            while (ldacq(&g_cnt[bsA[0]*S_ + t]) < GPB) { }
            while (ldacq(&g_cnt[bsA[1]*S_ + t]) < GPB) { }
        }
        __syncthreads();                                            // S4

        // ---- merge for both batches (scales via lane-parallel + shfl) ----
        #pragma unroll
        for (int pb = 0; pb < 2; ++pb) {
            const int b = bsA[pb];
            const float* base = partB + (b*GPB)*PST;
            float bmv = (lane < 16) ? __ldcg(base + lane*PST)     : NEGINF;
            float swv = (lane < 16) ? __ldcg(base + lane*PST + 1) : 0.f;
            float Mx = bmv;
            #pragma unroll
            for (int o = 8; o; o >>= 1) Mx = fmaxf(Mx, __shfl_xor_sync(0xffffffffu, Mx, o));
            Mx = __shfl_sync(0xffffffffu, Mx, 0);
            float sc[16];
            float Ssum = 0.f;
            #pragma unroll
            for (int i = 0; i < 16; ++i) {
                float bi = __shfl_sync(0xffffffffu, bmv, i);
                float si = __shfl_sync(0xffffffffu, swv, i);
                sc[i] = __expf(bi - Mx);
                Ssum += sc[i] * si;
            }
            float invS = 1.0f / Ssum;
            float pv = 0.f;
            #pragma unroll
            for (int i = 0; i < 16; ++i)
                pv += __ldcg(base + i*PST + 2 + tid) * sc[i];
            s_p[pb][tid] = pv * invS;
        }
        // candidate keys (half-block per batch)
        {
            const int pb = tid >> 7, c = tid & 127;
            const int b = bsA[pb];
            int i = c >> 3, j = c & 7;
            float cv = __ldcg(&partB[(b*GPB + i)*PST + 258 + j]);
            int   ci = __ldcg(&tidxB[(b*GPB + i)*8 + j]);
            s_ci[pb][c] = ci;
            unsigned fb = __float_as_uint(cv);
            fb ^= (fb & 0x80000000u) ? 0xFFFFFFFFu : 0x80000000u;
            s_pk[pb][c] = ((unsigned long long)fb << 32) | (unsigned)(~ci);
        }
        __syncthreads();                                            // S5

        // ---- global top-8 rank (half-block) + out/gate slice GEMV ----
        {
            const int pb = tid >> 7, c = tid & 127;
            unsigned long long me = s_pk[pb][c];
            int rk = 0;
            #pragma unroll 16
            for (int j = 0; j < 128; ++j) rk += (s_pk[pb][j] > me);
            if (rk < 8) s_sel[pb][rk] = s_ci[pb][c];
        }
        {
            const int pb = warp >> 2;                 // warps 0-3: pb0, 4-7: pb1
            const int w4 = warp & 3;
            const int k0 = w4 * 64;
            const float* Mp = (lane < 16) ? (Wv + dbase + lane)
                                          : (g_C + dbase + (lane - 16));
            float acc = 0.f;
            #pragma unroll
            for (int kk = 0; kk < 64; ++kk)
                acc += s_p[pb][k0 + kk] * Mp[(k0 + kk)*D_];
            s_red[pb][w4*32 + lane] = acc;
        }
        __syncthreads();                                            // S6

        // ---- finalize out + gate for both batches ----
        if ((tid & 127) < 32) {
            const int pb = tid >> 7, sub = tid & 31;
            const int b = bsA[pb];
            float tot = s_red[pb][sub] + s_red[pb][32 + sub]
                      + s_red[pb][64 + sub] + s_red[pb][96 + sub];
            if (sub < 16) {
                out[(b*S_ + t)*D_ + dbase + sub] = tot + __ldg(&bv[dbase + sub]);
            } else {
                int d = dbase + sub - 16;
                float z = g_xg[(b*S_ + t)*D_ + d] + g_bgc[d] + tot;
                g_gv[b*D_ + d] = 1.0f / (1.0f + __expf(-z));
            }
        }
        __syncthreads();                                            // S7
        if (tid == 0) {
            red_release(&g_cnt[B_*S_ + bsA[0]*S_ + t]);
            red_release(&g_cnt[B_*S_ + bsA[1]*S_ + t]);
        }
    }
}

// ----------------------------- launch -----------------------------
extern "C" void kernel_launch(void* const* d_in, const int* in_sizes, int n_in,
                              void* d_out, int out_size)
{
    const float* x      = (const float*)d_in[0];
    const float* memory = (const float*)d_in[1];
    const float* Wq     = (const float*)d_in[2];
    const float* bq     = (const float*)d_in[3];
    const float* Wk     = (const float*)d_in[4];
    // d_in[5] = bk : constant logit shift; softmax/top-k invariant -> unused
    const float* Wv     = (const float*)d_in[6];
    const float* bv     = (const float*)d_in[7];
    const float* Wg     = (const float*)d_in[8];
    const float* bg     = (const float*)d_in[9];
    float* out = (float*)d_out;

    mal_init<<<97, NT>>>(x, Wq, bq, Wk, Wv, bv, Wg, bg);
    mal_main<<<NBLK, NT>>>(x, memory, Wv, bv, out);
}

// round 12
// speedup vs baseline: 1.5989x; 1.5989x over previous
#include <cuda_runtime.h>

#define B_   8
#define S_   32
#define D_   256
#define M_   2048
#define GPB  16      // blocks per batch (slices of M)
#define RPB  128     // rows per slice
#define NT   256     // threads per block
#define PST  272     // floats per partial record
#define NBLK (B_*GPB)
#define NEGINF (__int_as_float(0xff800000))

// ----------------------------- device state -----------------------------
__device__ float g_mem [B_*M_*D_];        // per-batch working rows (filled from regs at t=0)
__device__ float g_qt  [B_*S_*D_];        // (x@Wq+bq)@Wk^T / sqrt(D)
__device__ float g_xg  [B_*S_*D_];        // x@Wg1 + bg
__device__ float g_bgc [D_];              // bv@Wg2
__device__ float g_C   [D_*D_];           // Wv@Wg2
__device__ float g_part[2*B_*GPB*PST];    // partials, double buffered by step parity
__device__ int   g_tidx[2*B_*GPB*8];      // top8 global row ids
__device__ float g_gv  [B_*D_];           // gate vector per batch
__device__ int   g_cnt [2*B_*S_];         // cA[256] then cB[256], zeroed by init

__device__ __forceinline__ int ldacq(const int* p) {
    int v;
    asm volatile("ld.acquire.gpu.global.b32 %0, [%1];" : "=r"(v) : "l"(p) : "memory");
    return v;
}
// release-arrive without the L1D-flushing CCTL.IVALL of __threadfence()
__device__ __forceinline__ void red_release(int* p) {
    asm volatile("red.release.gpu.global.add.s32 [%0], %1;" :: "l"(p), "r"(1) : "memory");
}
__device__ __forceinline__ float dot8(float4 a, float4 b, float4 qa, float4 qb) {
    return a.x*qa.x + a.y*qa.y + a.z*qa.z + a.w*qa.w
         + b.x*qb.x + b.y*qb.y + b.z*qb.z + b.w*qb.w;
}
__device__ __forceinline__ float wredsum(float v) {
    #pragma unroll
    for (int o = 16; o; o >>= 1) v += __shfl_xor_sync(0xffffffffu, v, o);
    return v;
}

// ----------------------------- init kernel (97 blocks) -----------------------------
__global__ void __launch_bounds__(NT)
mal_init(const float* __restrict__ x,  const float* __restrict__ Wq,
         const float* __restrict__ bq, const float* __restrict__ Wk,
         const float* __restrict__ Wv, const float* __restrict__ bv,
         const float* __restrict__ Wg, const float* __restrict__ bg)
{
    __shared__ float s_buf[2048];
    const int bid = blockIdx.x, tid = threadIdx.x;
    const int lane = tid & 31, warp = tid >> 5;

    if (bid == 96) {
        for (int i = tid; i < 2*B_*S_; i += NT) g_cnt[i] = 0;
        float acc = 0.f;
        #pragma unroll 16
        for (int j = 0; j < D_; ++j) acc += bv[j] * Wg[(D_ + j)*D_ + tid];
        g_bgc[tid] = acc;
        return;
    }
    const int which = bid >> 5;               // 0: qt-chain, 1: xg, 2: C
    const int sub   = bid & 31;
    const int r0    = sub * 8;
    const float* srcA = (which == 2) ? (Wv + r0*D_) : (x + r0*D_);
    for (int i = tid; i < 2048; i += NT) s_buf[i] = srcA[i];
    __syncthreads();
    const float* Wcol = (which == 0) ? Wq : (which == 1 ? Wg : (Wg + D_*D_));
    float acc[8];
    #pragma unroll
    for (int r = 0; r < 8; ++r) acc[r] = 0.f;
    #pragma unroll 16
    for (int j = 0; j < D_; ++j) {
        float w = Wcol[j*D_ + tid];
        #pragma unroll
        for (int r = 0; r < 8; ++r) acc[r] += s_buf[r*D_ + j] * w;
    }
    if (which == 1) {
        float bb = bg[tid];
        #pragma unroll
        for (int r = 0; r < 8; ++r) g_xg[(r0+r)*D_ + tid] = acc[r] + bb;
    } else if (which == 2) {
        #pragma unroll
        for (int r = 0; r < 8; ++r) g_C[(r0+r)*D_ + tid] = acc[r];
    } else {
        float bb = bq[tid];
        __syncthreads();
        #pragma unroll
        for (int r = 0; r < 8; ++r) s_buf[r*D_ + tid] = acc[r] + bb;
        __syncthreads();
        float4 t0[8], t1[8];
        #pragma unroll
        for (int r = 0; r < 8; ++r) {
            t0[r] = *(const float4*)(s_buf + r*D_ + lane*4);
            t1[r] = *(const float4*)(s_buf + r*D_ + 128 + lane*4);
        }
        int d = warp * 32;
        float4 w0 = *(const float4*)(Wk + d*D_ + lane*4);
        float4 w1 = *(const float4*)(Wk + d*D_ + 128 + lane*4);
        for (int dd = 0; dd < 32; ++dd) {
            float4 c0 = w0, c1 = w1;
            if (dd < 31) {
                w0 = *(const float4*)(Wk + (d+1)*D_ + lane*4);
                w1 = *(const float4*)(Wk + (d+1)*D_ + 128 + lane*4);
            }
            float dt[8];
            #pragma unroll
            for (int r = 0; r < 8; ++r) {
                dt[r] = t0[r].x*c0.x + t0[r].y*c0.y + t0[r].z*c0.z + t0[r].w*c0.w
                      + t1[r].x*c1.x + t1[r].y*c1.y + t1[r].z*c1.z + t1[r].w*c1.w;
                dt[r] = wredsum(dt[r]);
            }
            if (lane == 0) {
                #pragma unroll
                for (int r = 0; r < 8; ++r) g_qt[(r0+r)*D_ + d] = dt[r] * 0.0625f;
            }
            ++d;
        }
    }
}

// ----------------------------- main persistent kernel -----------------------------
__global__ void __launch_bounds__(NT, 1)
mal_main(const float* __restrict__ x, const float* __restrict__ memory,
         const float* __restrict__ Wv, const float* __restrict__ bv,
         float* __restrict__ out)
{
    __shared__ float s_wacc[8][D_];
    __shared__ float s_wm[8], s_ws[8];
    __shared__ float s_lg[2][128];                 // logits, double buffered by step
    __shared__ unsigned long long s_cand[32];      // top-8-per-warp survivors
    __shared__ int   s_sel[8];
    __shared__ float s_p[D_];
    __shared__ float s_red[NT];

    const int tid  = threadIdx.x, lane = tid & 31, warp = tid >> 5;
    const int bid  = blockIdx.x;
    const int b    = bid >> 4;
    const int blk  = bid & 15;
    int* cA        = g_cnt + b * S_;
    int* cB        = g_cnt + B_*S_ + b * S_;
    const int d0   = lane * 4;
    const int d1   = 128 + lane * 4;
    float* rowp    = g_mem + ((size_t)b*M_ + blk*RPB + warp*16) * D_;

    float dts[16];
    float mw;

    // ---- prologue: logits for t=0, rows copied memory -> g_mem ----
    {
        const float4 qa = *(const float4*)(g_qt + (b*S_)*D_ + d0);
        const float4 qb = *(const float4*)(g_qt + (b*S_)*D_ + d1);
        const float* src = memory + (blk*RPB + warp*16) * D_;
        mw = NEGINF;
        #pragma unroll
        for (int r = 0; r < 16; ++r) {
            float4 fa = *(const float4*)(src + r*D_ + d0);
            float4 fb = *(const float4*)(src + r*D_ + d1);
            *(float4*)(rowp + r*D_ + d0) = fa;
            *(float4*)(rowp + r*D_ + d1) = fb;
            float dt = wredsum(dot8(fa, fb, qa, qb));
            dts[r] = dt;
            mw = fmaxf(mw, dt);
            if (lane == 0) s_lg[0][warp*16 + r] = dt;
        }
    }

    for (int t = 0; t < S_; ++t) {
        const int cur = t & 1, nxt = cur ^ 1;
        float* partbase = g_part + cur*(B_*GPB*PST);
        float* part     = partbase + bid * PST;
        int*   tidx     = g_tidx + cur*(B_*GPB*8);

        // ---- fix: owners apply step t-1's gated updates, correct dirty logits ----
        if (t > 0) {
            bool own = false;
            #pragma unroll
            for (int k = 0; k < 8; ++k) own |= ((s_sel[k] >> 7) == blk);
            if (own) {                                   // block-uniform branch
                if (tid == 0) { while (ldacq(&cB[t-1]) < GPB) { } }
                __syncthreads();
                float4 g0 = __ldcg((const float4*)(g_gv + b*D_ + d0));
                float4 g1 = __ldcg((const float4*)(g_gv + b*D_ + d1));
                float4 x0 = __ldg ((const float4*)(x + (size_t)(b*S_ + t-1)*D_ + d0));
                float4 x1 = __ldg ((const float4*)(x + (size_t)(b*S_ + t-1)*D_ + d1));
                const float4 qa = *(const float4*)(g_qt + (b*S_ + t)*D_ + d0);
                const float4 qb = *(const float4*)(g_qt + (b*S_ + t)*D_ + d1);
                #pragma unroll
                for (int k = 0; k < 8; ++k) {
                    int gi = s_sel[k];
                    if ((gi >> 7) == blk && ((gi >> 4) & 7) == warp) {
                        int r = gi & 15;
                        float4 fa = *(float4*)(rowp + r*D_ + d0);
                        float4 fb = *(float4*)(rowp + r*D_ + d1);
                        fa.x += g0.x*(x0.x - fa.x); fa.y += g0.y*(x0.y - fa.y);
                        fa.z += g0.z*(x0.z - fa.z); fa.w += g0.w*(x0.w - fa.w);
                        fb.x += g1.x*(x1.x - fb.x); fb.y += g1.y*(x1.y - fb.y);
                        fb.z += g1.z*(x1.z - fb.z); fb.w += g1.w*(x1.w - fb.w);
                        *(float4*)(rowp + r*D_ + d0) = fa;
                        *(float4*)(rowp + r*D_ + d1) = fb;
                        float dt = wredsum(dot8(fa, fb, qa, qb));
                        dts[r] = dt;
                        if (lane == 0) s_lg[cur][warp*16 + r] = dt;
                    }
                }
                mw = dts[0];
                #pragma unroll
                for (int r = 1; r < 16; ++r) mw = fmaxf(mw, dts[r]);
            }
        }

        // ---- fused sweep: e-weighted row sum (step t) + logits (step t+1) ----
        {
            float e[16], sw = 0.f;
            #pragma unroll
            for (int r = 0; r < 16; ++r) { e[r] = __expf(dts[r] - mw); sw += e[r]; }
            const int tn = (t + 1 < S_) ? t + 1 : t;
            const float4 qa = *(const float4*)(g_qt + (b*S_ + tn)*D_ + d0);
            const float4 qb = *(const float4*)(g_qt + (b*S_ + tn)*D_ + d1);
            float4 A = {0,0,0,0}, Bb = {0,0,0,0};
            float nmw = NEGINF;
            #pragma unroll
            for (int r = 0; r < 16; ++r) {
                float4 fa = *(const float4*)(rowp + r*D_ + d0);
                float4 fb = *(const float4*)(rowp + r*D_ + d1);
                A.x += e[r]*fa.x; A.y += e[r]*fa.y; A.z += e[r]*fa.z; A.w += e[r]*fa.w;
                Bb.x += e[r]*fb.x; Bb.y += e[r]*fb.y; Bb.z += e[r]*fb.z; Bb.w += e[r]*fb.w;
                float dt = wredsum(dot8(fa, fb, qa, qb));
                dts[r] = dt;
                nmw = fmaxf(nmw, dt);
                if (lane == 0) s_lg[nxt][warp*16 + r] = dt;
            }
            *(float4*)&s_wacc[warp][d0] = A;
            *(float4*)&s_wacc[warp][d1] = Bb;
            if (lane == 0) { s_wm[warp] = mw; s_ws[warp] = sw; }
            mw = nmw;
        }
        __syncthreads();                                            // S1

        // ---- stage 2: rescaled partial + key build ----
        unsigned long long key1 = 0;
        {
            float m0 = fmaxf(fmaxf(s_wm[0], s_wm[1]), fmaxf(s_wm[2], s_wm[3]));
            float m1 = fmaxf(fmaxf(s_wm[4], s_wm[5]), fmaxf(s_wm[6], s_wm[7]));
            float bm = fmaxf(m0, m1);
            float sc[8];
            #pragma unroll
            for (int w = 0; w < 8; ++w) sc[w] = __expf(s_wm[w] - bm);
            float pv = 0.f;
            #pragma unroll
            for (int w = 0; w < 8; ++w) pv += s_wacc[w][tid] * sc[w];
            part[2 + tid] = pv;
            if (tid == 0) {
                float sw = 0.f;
                #pragma unroll
                for (int w = 0; w < 8; ++w) sw += s_ws[w] * sc[w];
                part[0] = bm; part[1] = sw;
            }
            if (tid < 128) {
                unsigned fb = __float_as_uint(s_lg[cur][tid]);
                fb ^= (fb & 0x80000000u) ? 0xFFFFFFFFu : 0x80000000u;
                key1 = ((unsigned long long)fb << 32) | (unsigned)(~tid);
            }
        }
        // ---- local top-8, stage A: 31-rotation rank within each of 4 warps ----
        if (tid < 128) {
            int rk = 0;
            #pragma unroll
            for (int i = 1; i < 32; ++i) {
                unsigned long long o = __shfl_sync(0xffffffffu, key1, (lane + i) & 31);
                rk += (o > key1);
            }
            if (rk < 8) s_cand[warp*8 + rk] = key1;
        }
        __syncthreads();                                            // S2
        // ---- local top-8, stage B: rank among 32 survivors (warp 0) ----
        if (warp == 0) {
            unsigned long long k2 = s_cand[lane];
            int rk = 0;
            #pragma unroll
            for (int i = 1; i < 32; ++i) {
                unsigned long long o = __shfl_sync(0xffffffffu, k2, (lane + i) & 31);
                rk += (o > k2);
            }
            if (rk < 8) {
                unsigned fb = (unsigned)(k2 >> 32);
                fb ^= (fb & 0x80000000u) ? 0x80000000u : 0xFFFFFFFFu;
                int c = (int)(~((unsigned)k2)) & 127;
                part[258 + rk] = __uint_as_float(fb);
                tidx[bid*8 + rk] = blk*RPB + c;
            }
        }
        __syncthreads();                                            // S3
        // ---- global barrier A ----
        if (tid == 0) {
            red_release(&cA[t]);
            while (ldacq(&cA[t]) < GPB) { }
        }
        __syncthreads();                                            // S4

        // ---- merge: every thread computes scales itself ----
        {
            float bmv[16], swv[16];
            #pragma unroll
            for (int i = 0; i < 16; ++i) {
                bmv[i] = __ldcg(&partbase[(b*GPB + i)*PST]);
                swv[i] = __ldcg(&partbase[(b*GPB + i)*PST + 1]);
            }
            float Mx = bmv[0];
            #pragma unroll
            for (int i = 1; i < 16; ++i) Mx = fmaxf(Mx, bmv[i]);
            float Ssum = 0.f, sc[16];
            #pragma unroll
            for (int i = 0; i < 16; ++i) { sc[i] = __expf(bmv[i] - Mx); Ssum += sc[i]*swv[i]; }
            float invS = 1.0f / Ssum;
            float pv = 0.f;
            #pragma unroll
            for (int i = 0; i < 16; ++i)
                pv += __ldcg(&partbase[(b*GPB + i)*PST + 2 + tid]) * sc[i];
            s_p[tid] = pv * invS;
        }
        // ---- global top-8, stage A (candidates from all 16 blocks) ----
        if (tid < 128) {
            int i = tid >> 3, j = tid & 7;
            float cv = __ldcg(&partbase[(b*GPB + i)*PST + 258 + j]);
            int   ci = __ldcg(&tidx[(b*GPB + i)*8 + j]);
            unsigned fb = __float_as_uint(cv);
            fb ^= (fb & 0x80000000u) ? 0xFFFFFFFFu : 0x80000000u;
            unsigned long long key2 = ((unsigned long long)fb << 32) | (unsigned)(~ci);
            int rk = 0;
            #pragma unroll
            for (int i2 = 1; i2 < 32; ++i2) {
                unsigned long long o = __shfl_sync(0xffffffffu, key2, (lane + i2) & 31);
                rk += (o > key2);
            }
            if (rk < 8) s_cand[warp*8 + rk] = key2;
        }
        __syncthreads();                                            // S5
        // ---- global top-8, stage B (warp 0) + out/gate slice GEMV (all warps) ----
        if (warp == 0) {
            unsigned long long k2 = s_cand[lane];
            int rk = 0;
            #pragma unroll
            for (int i = 1; i < 32; ++i) {
                unsigned long long o = __shfl_sync(0xffffffffu, k2, (lane + i) & 31);
                rk += (o > k2);
            }
            if (rk < 8) s_sel[rk] = (int)(~((unsigned)k2));
        }
        {
            const int dbase = blk * 16;
            const float* Mp = (lane < 16) ? (Wv + dbase + lane)
                                          : (g_C + dbase + (lane - 16));
            float acc = 0.f;
            const int k0 = warp * 32;
            #pragma unroll
            for (int kk = 0; kk < 32; ++kk)
                acc += s_p[k0 + kk] * Mp[(k0 + kk)*D_];
            s_red[tid] = acc;
        }
        __syncthreads();                                            // S6
        if (tid < 32) {
            float tot = 0.f;
            #pragma unroll
            for (int w = 0; w < 8; ++w) tot += s_red[w*32 + tid];
            const int dbase = blk * 16;
            if (tid < 16) {
                out[(b*S_ + t)*D_ + dbase + tid] = tot + __ldg(&bv[dbase + tid]);
            } else {
                int d = dbase + tid - 16;
                float z = g_xg[(b*S_ + t)*D_ + d] + g_bgc[d] + tot;
                g_gv[b*D_ + d] = 1.0f / (1.0f + __expf(-z));
            }
        }
        __syncthreads();                                            // S7
        if (tid == 0) red_release(&cB[t]);   // owners wait at t+1
    }
}

// ----------------------------- launch -----------------------------
extern "C" void kernel_launch(void* const* d_in, const int* in_sizes, int n_in,
                              void* d_out, int out_size)
{
    const float* x      = (const float*)d_in[0];
    const float* memory = (const float*)d_in[1];
    const float* Wq     = (const float*)d_in[2];
    const float* bq     = (const float*)d_in[3];
    const float* Wk     = (const float*)d_in[4];
    // d_in[5] = bk : constant logit shift; softmax/top-k invariant -> unused
    const float* Wv     = (const float*)d_in[6];
    const float* bv     = (const float*)d_in[7];
    const float* Wg     = (const float*)d_in[8];
    const float* bg     = (const float*)d_in[9];
    float* out = (float*)d_out;

    mal_init<<<97, NT>>>(x, Wq, bq, Wk, Wv, bv, Wg, bg);
    mal_main<<<NBLK, NT>>>(x, memory, Wv, bv, out);
}

// round 13
// speedup vs baseline: 1.6234x; 1.0153x over previous
#include <cuda_runtime.h>

#define B_   8
#define S_   32
#define D_   256
#define M_   2048
#define GPB  16      // blocks per batch (slices of M)
#define RPB  128     // rows per slice
#define NT   256     // threads per block
#define PST  272     // floats per partial record
#define NBLK (B_*GPB)
#define NEGINF (__int_as_float(0xff800000))
#define FULLM 0xffffffffu

// ----------------------------- device state -----------------------------
__device__ float g_mem [B_*M_*D_];        // per-batch working rows (filled from regs at t=0)
__device__ float g_qt  [B_*S_*D_];        // (x@Wq+bq)@Wk^T / sqrt(D)
__device__ float g_xg  [B_*S_*D_];        // x@Wg1 + bg
__device__ float g_bgc [D_];              // bv@Wg2
__device__ float g_C   [D_*D_];           // Wv@Wg2
__device__ float g_part[2*B_*GPB*PST];    // partials, double buffered by step parity
__device__ int   g_tidx[2*B_*GPB*8];      // top8 global row ids
__device__ float g_gv  [B_*D_];           // gate vector per batch
__device__ int   g_cnt [2*B_*S_];         // cA[256] then cB[256], zeroed by init

__device__ __forceinline__ int ldacq(const int* p) {
    int v;
    asm volatile("ld.acquire.gpu.global.b32 %0, [%1];" : "=r"(v) : "l"(p) : "memory");
    return v;
}
// release-arrive without the L1D-flushing CCTL.IVALL of __threadfence()
__device__ __forceinline__ void red_release(int* p) {
    asm volatile("red.release.gpu.global.add.s32 [%0], %1;" :: "l"(p), "r"(1) : "memory");
}
__device__ __forceinline__ float dot8(float4 a, float4 b, float4 qa, float4 qb) {
    return a.x*qa.x + a.y*qa.y + a.z*qa.z + a.w*qa.w
         + b.x*qb.x + b.y*qb.y + b.z*qb.z + b.w*qb.w;
}
__device__ __forceinline__ float wredsum(float v) {
    #pragma unroll
    for (int o = 16; o; o >>= 1) v += __shfl_xor_sync(FULLM, v, o);
    return v;
}
__device__ __forceinline__ float wredmax(float v) {
    #pragma unroll
    for (int o = 16; o; o >>= 1) v = fmaxf(v, __shfl_xor_sync(FULLM, v, o));
    return v;
}

// ----------------------------- init kernel (97 blocks) -----------------------------
__global__ void __launch_bounds__(NT)
mal_init(const float* __restrict__ x,  const float* __restrict__ Wq,
         const float* __restrict__ bq, const float* __restrict__ Wk,
         const float* __restrict__ Wv, const float* __restrict__ bv,
         const float* __restrict__ Wg, const float* __restrict__ bg)
{
    __shared__ float s_buf[2048];
    const int bid = blockIdx.x, tid = threadIdx.x;
    const int lane = tid & 31, warp = tid >> 5;

    if (bid == 96) {
        for (int i = tid; i < 2*B_*S_; i += NT) g_cnt[i] = 0;
        float acc = 0.f;
        #pragma unroll 16
        for (int j = 0; j < D_; ++j) acc += bv[j] * Wg[(D_ + j)*D_ + tid];
        g_bgc[tid] = acc;
        return;
    }
    const int which = bid >> 5;               // 0: qt-chain, 1: xg, 2: C
    const int sub   = bid & 31;
    const int r0    = sub * 8;
    const float* srcA = (which == 2) ? (Wv + r0*D_) : (x + r0*D_);
    for (int i = tid; i < 2048; i += NT) s_buf[i] = srcA[i];
    __syncthreads();
    const float* Wcol = (which == 0) ? Wq : (which == 1 ? Wg : (Wg + D_*D_));
    float acc[8];
    #pragma unroll
    for (int r = 0; r < 8; ++r) acc[r] = 0.f;
    #pragma unroll 16
    for (int j = 0; j < D_; ++j) {
        float w = Wcol[j*D_ + tid];
        #pragma unroll
        for (int r = 0; r < 8; ++r) acc[r] += s_buf[r*D_ + j] * w;
    }
    if (which == 1) {
        float bb = bg[tid];
        #pragma unroll
        for (int r = 0; r < 8; ++r) g_xg[(r0+r)*D_ + tid] = acc[r] + bb;
    } else if (which == 2) {
        #pragma unroll
        for (int r = 0; r < 8; ++r) g_C[(r0+r)*D_ + tid] = acc[r];
    } else {
        float bb = bq[tid];
        __syncthreads();
        #pragma unroll
        for (int r = 0; r < 8; ++r) s_buf[r*D_ + tid] = acc[r] + bb;
        __syncthreads();
        float4 t0[8], t1[8];
        #pragma unroll
        for (int r = 0; r < 8; ++r) {
            t0[r] = *(const float4*)(s_buf + r*D_ + lane*4);
            t1[r] = *(const float4*)(s_buf + r*D_ + 128 + lane*4);
        }
        int d = warp * 32;
        float4 w0 = *(const float4*)(Wk + d*D_ + lane*4);
        float4 w1 = *(const float4*)(Wk + d*D_ + 128 + lane*4);
        for (int dd = 0; dd < 32; ++dd) {
            float4 c0 = w0, c1 = w1;
            if (dd < 31) {
                w0 = *(const float4*)(Wk + (d+1)*D_ + lane*4);
                w1 = *(const float4*)(Wk + (d+1)*D_ + 128 + lane*4);
            }
            float dt[8];
            #pragma unroll
            for (int r = 0; r < 8; ++r) {
                dt[r] = t0[r].x*c0.x + t0[r].y*c0.y + t0[r].z*c0.z + t0[r].w*c0.w
                      + t1[r].x*c1.x + t1[r].y*c1.y + t1[r].z*c1.z + t1[r].w*c1.w;
                dt[r] = wredsum(dt[r]);
            }
            if (lane == 0) {
                #pragma unroll
                for (int r = 0; r < 8; ++r) g_qt[(r0+r)*D_ + d] = dt[r] * 0.0625f;
            }
            ++d;
        }
    }
}

// ----------------------------- main persistent kernel -----------------------------
__global__ void __launch_bounds__(NT, 1)
mal_main(const float* __restrict__ x, const float* __restrict__ memory,
         const float* __restrict__ Wv, const float* __restrict__ bv,
         float* __restrict__ out)
{
    __shared__ float s_wacc[8][D_];
    __shared__ float s_wm[8], s_ws[8];
    __shared__ float s_lg[2][128];                 // logits, double buffered by step
    __shared__ unsigned long long s_cand[32];      // top-8-per-warp survivors
    __shared__ int   s_sel[8];
    __shared__ float s_p[D_];
    __shared__ float s_red[NT];

    const int tid  = threadIdx.x, lane = tid & 31, warp = tid >> 5;
    const int bid  = blockIdx.x;
    const int b    = bid >> 4;
    const int blk  = bid & 15;
    int* cA        = g_cnt + b * S_;
    int* cB        = g_cnt + B_*S_ + b * S_;
    const int d0   = lane * 4;
    const int d1   = 128 + lane * 4;
    float* rowp    = g_mem + ((size_t)b*M_ + blk*RPB + warp*16) * D_;

    float dts[16];
    float mw;

    // ---- prologue: logits for t=0, rows copied memory -> g_mem ----
    {
        const float4 qa = *(const float4*)(g_qt + (b*S_)*D_ + d0);
        const float4 qb = *(const float4*)(g_qt + (b*S_)*D_ + d1);
        const float* src = memory + (blk*RPB + warp*16) * D_;
        mw = NEGINF;
        #pragma unroll
        for (int r = 0; r < 16; ++r) {
            float4 fa = *(const float4*)(src + r*D_ + d0);
            float4 fb = *(const float4*)(src + r*D_ + d1);
            *(float4*)(rowp + r*D_ + d0) = fa;
            *(float4*)(rowp + r*D_ + d1) = fb;
            float dt = wredsum(dot8(fa, fb, qa, qb));
            dts[r] = dt;
            mw = fmaxf(mw, dt);
            if (lane == 0) s_lg[0][warp*16 + r] = dt;
        }
        __syncwarp();
    }

    for (int t = 0; t < S_; ++t) {
        const int cur = t & 1, nxt = cur ^ 1;
        float* partbase = g_part + cur*(B_*GPB*PST);
        float* part     = partbase + bid * PST;
        int*   tidx     = g_tidx + cur*(B_*GPB*8);

        // ---- owners apply step t-1's gated updates, correct dirty logits ----
        if (t > 0) {
            bool own = false;
            #pragma unroll
            for (int k = 0; k < 8; ++k) own |= ((s_sel[k] >> 7) == blk);
            if (own) {                                   // block-uniform branch
                if (tid == 0) { while (ldacq(&cB[t-1]) < GPB) { } }
                __syncthreads();
                float4 g0 = __ldcg((const float4*)(g_gv + b*D_ + d0));
                float4 g1 = __ldcg((const float4*)(g_gv + b*D_ + d1));
                float4 x0 = __ldg ((const float4*)(x + (size_t)(b*S_ + t-1)*D_ + d0));
                float4 x1 = __ldg ((const float4*)(x + (size_t)(b*S_ + t-1)*D_ + d1));
                const float4 qa = *(const float4*)(g_qt + (b*S_ + t)*D_ + d0);
                const float4 qb = *(const float4*)(g_qt + (b*S_ + t)*D_ + d1);
                #pragma unroll
                for (int k = 0; k < 8; ++k) {
                    int gi = s_sel[k];
                    if ((gi >> 7) == blk && ((gi >> 4) & 7) == warp) {
                        int r = gi & 15;
                        float4 fa = *(float4*)(rowp + r*D_ + d0);
                        float4 fb = *(float4*)(rowp + r*D_ + d1);
                        fa.x += g0.x*(x0.x - fa.x); fa.y += g0.y*(x0.y - fa.y);
                        fa.z += g0.z*(x0.z - fa.z); fa.w += g0.w*(x0.w - fa.w);
                        fb.x += g1.x*(x1.x - fb.x); fb.y += g1.y*(x1.y - fb.y);
                        fb.z += g1.z*(x1.z - fb.z); fb.w += g1.w*(x1.w - fb.w);
                        *(float4*)(rowp + r*D_ + d0) = fa;
                        *(float4*)(rowp + r*D_ + d1) = fb;
                        float dt = wredsum(dot8(fa, fb, qa, qb));
                        dts[r] = dt;
                        if (lane == 0) s_lg[cur][warp*16 + r] = dt;
                    }
                }
                mw = dts[0];
                #pragma unroll
                for (int r = 1; r < 16; ++r) mw = fmaxf(mw, dts[r]);
                __syncwarp();
            }
        }

        // ---- fused sweep: e-weighted row sum (step t) + logits (step t+1) ----
        {
            // lane-parallel exp over this warp's 16 warp-uniform logits
            float ev = (lane < 16) ? __expf(s_lg[cur][warp*16 + lane] - mw) : 0.f;
            float sw = wredsum(ev);
            const int tn = (t + 1 < S_) ? t + 1 : t;
            const float4 qa = *(const float4*)(g_qt + (b*S_ + tn)*D_ + d0);
            const float4 qb = *(const float4*)(g_qt + (b*S_ + tn)*D_ + d1);
            float4 A = {0,0,0,0}, Bb = {0,0,0,0};
            float nmw = NEGINF;
            #pragma unroll
            for (int r = 0; r < 16; ++r) {
                float er = __shfl_sync(FULLM, ev, r);
                float4 fa = *(const float4*)(rowp + r*D_ + d0);
                float4 fb = *(const float4*)(rowp + r*D_ + d1);
                A.x += er*fa.x; A.y += er*fa.y; A.z += er*fa.z; A.w += er*fa.w;
                Bb.x += er*fb.x; Bb.y += er*fb.y; Bb.z += er*fb.z; Bb.w += er*fb.w;
                float dt = wredsum(dot8(fa, fb, qa, qb));
                dts[r] = dt;
                nmw = fmaxf(nmw, dt);
                if (lane == 0) s_lg[nxt][warp*16 + r] = dt;
            }
            *(float4*)&s_wacc[warp][d0] = A;
            *(float4*)&s_wacc[warp][d1] = Bb;
            if (lane == 0) { s_wm[warp] = mw; s_ws[warp] = sw; }
            mw = nmw;
        }
        __syncthreads();                                            // S1

        // ---- stage 2: rescaled partial via lane-parallel scales ----
        unsigned long long key1 = 0;
        {
            float m0 = fmaxf(fmaxf(s_wm[0], s_wm[1]), fmaxf(s_wm[2], s_wm[3]));
            float m1 = fmaxf(fmaxf(s_wm[4], s_wm[5]), fmaxf(s_wm[6], s_wm[7]));
            float bm = fmaxf(m0, m1);
            float scv = (lane < 8) ? __expf(s_wm[lane] - bm) : 0.f;
            float pv = 0.f;
            #pragma unroll
            for (int w = 0; w < 8; ++w)
                pv += s_wacc[w][tid] * __shfl_sync(FULLM, scv, w);
            part[2 + tid] = pv;
            if (warp == 0) {
                float t8 = (lane < 8) ? scv * s_ws[lane] : 0.f;
                t8 = wredsum(t8);
                if (lane == 0) { part[0] = bm; part[1] = t8; }
            }
            if (tid < 128) {
                unsigned fb = __float_as_uint(s_lg[cur][tid]);
                fb ^= (fb & 0x80000000u) ? 0xFFFFFFFFu : 0x80000000u;
                key1 = ((unsigned long long)fb << 32) | (unsigned)(~tid);
            }
        }
        // ---- local top-8, stage A: 31-rotation rank within each of 4 warps ----
        if (tid < 128) {
            int rk = 0;
            #pragma unroll
            for (int i = 1; i < 32; ++i) {
                unsigned long long o = __shfl_sync(FULLM, key1, (lane + i) & 31);
                rk += (o > key1);
            }
            if (rk < 8) s_cand[warp*8 + rk] = key1;
        }
        __syncthreads();                                            // S2
        // ---- local top-8, stage B: rank among 32 survivors (warp 0) ----
        if (warp == 0) {
            unsigned long long k2 = s_cand[lane];
            int rk = 0;
            #pragma unroll
            for (int i = 1; i < 32; ++i) {
                unsigned long long o = __shfl_sync(FULLM, k2, (lane + i) & 31);
                rk += (o > k2);
            }
            if (rk < 8) {
                unsigned fb = (unsigned)(k2 >> 32);
                fb ^= (fb & 0x80000000u) ? 0x80000000u : 0xFFFFFFFFu;
                int c = (int)(~((unsigned)k2)) & 127;
                part[258 + rk] = __uint_as_float(fb);
                tidx[bid*8 + rk] = blk*RPB + c;
            }
        }
        __syncthreads();                                            // S3
        // ---- global barrier A ----
        if (tid == 0) {
            red_release(&cA[t]);
            while (ldacq(&cA[t]) < GPB) { }
        }
        __syncthreads();                                            // S4

        // ---- merge: lane-parallel scales, shfl-broadcast pv loop ----
        {
            float lv = (lane < 16) ? __ldcg(&partbase[(b*GPB + lane)*PST])     : NEGINF;
            float sv = (lane < 16) ? __ldcg(&partbase[(b*GPB + lane)*PST + 1]) : 0.f;
            float Mx = wredmax(lv);
            float scv2 = (lane < 16) ? __expf(lv - Mx) : 0.f;
            float Ssum = wredsum(scv2 * sv);
            float invS = 1.0f / Ssum;
            float pv = 0.f;
            #pragma unroll
            for (int i = 0; i < 16; ++i)
                pv += __ldcg(&partbase[(b*GPB + i)*PST + 2 + tid]) * __shfl_sync(FULLM, scv2, i);
            s_p[tid] = pv * invS;
        }
        // ---- global top-8, stage A (candidates from all 16 blocks) ----
        if (tid < 128) {
            int i = tid >> 3, j = tid & 7;
            float cv = __ldcg(&partbase[(b*GPB + i)*PST + 258 + j]);
            int   ci = __ldcg(&tidx[(b*GPB + i)*8 + j]);
            unsigned fb = __float_as_uint(cv);
            fb ^= (fb & 0x80000000u) ? 0xFFFFFFFFu : 0x80000000u;
            unsigned long long key2 = ((unsigned long long)fb << 32) | (unsigned)(~ci);
            int rk = 0;
            #pragma unroll
            for (int i2 = 1; i2 < 32; ++i2) {
                unsigned long long o = __shfl_sync(FULLM, key2, (lane + i2) & 31);
                rk += (o > key2);
            }
            if (rk < 8) s_cand[warp*8 + rk] = key2;
        }
        __syncthreads();                                            // S5
        // ---- global top-8, stage B (warp 0) + out/gate slice GEMV (all warps) ----
        if (warp == 0) {
            unsigned long long k2 = s_cand[lane];
            int rk = 0;
            #pragma unroll
            for (int i = 1; i < 32; ++i) {
                unsigned long long o = __shfl_sync(FULLM, k2, (lane + i) & 31);
                rk += (o > k2);
            }
            if (rk < 8) s_sel[rk] = (int)(~((unsigned)k2));
        }
        {
            const int dbase = blk * 16;
            const float* Mp = (lane < 16) ? (Wv + dbase + lane)
                                          : (g_C + dbase + (lane - 16));
            float acc = 0.f;
            const int k0 = warp * 32;
            #pragma unroll
            for (int kk = 0; kk < 32; ++kk)
                acc += s_p[k0 + kk] * Mp[(k0 + kk)*D_];
            s_red[tid] = acc;
        }
        __syncthreads();                                            // S6
        if (tid < 32) {
            float tot = 0.f;
            #pragma unroll
            for (int w = 0; w < 8; ++w) tot += s_red[w*32 + tid];
            const int dbase = blk * 16;
            if (tid < 16) {
                out[(b*S_ + t)*D_ + dbase + tid] = tot + __ldg(&bv[dbase + tid]);
            } else {
                int d = dbase + tid - 16;
                float z = g_xg[(b*S_ + t)*D_ + d] + g_bgc[d] + tot;
                g_gv[b*D_ + d] = 1.0f / (1.0f + __expf(-z));
            }
        }
        __syncthreads();                                            // S7
        if (tid == 0) red_release(&cB[t]);   // owners wait at t+1
    }
}

// ----------------------------- launch -----------------------------
extern "C" void kernel_launch(void* const* d_in, const int* in_sizes, int n_in,
                              void* d_out, int out_size)
{
    const float* x      = (const float*)d_in[0];
    const float* memory = (const float*)d_in[1];
    const float* Wq     = (const float*)d_in[2];
    const float* bq     = (const float*)d_in[3];
    const float* Wk     = (const float*)d_in[4];
    // d_in[5] = bk : constant logit shift; softmax/top-k invariant -> unused
    const float* Wv     = (const float*)d_in[6];
    const float* bv     = (const float*)d_in[7];
    const float* Wg     = (const float*)d_in[8];
    const float* bg     = (const float*)d_in[9];
    float* out = (float*)d_out;

    mal_init<<<97, NT>>>(x, Wq, bq, Wk, Wv, bv, Wg, bg);
    mal_main<<<NBLK, NT>>>(x, memory, Wv, bv, out);
}

// round 14
// speedup vs baseline: 1.7249x; 1.0626x over previous
#include <cuda_runtime.h>

#define B_   8
#define S_   32
#define D_   256
#define M_   2048
#define GPB  16      // blocks per batch (slices of M)
#define RPB  128     // rows per slice
#define NT   256     // threads per block
#define PST  272     // floats per partial record
#define NBLK (B_*GPB)
#define NEGINF (__int_as_float(0xff800000))
#define FULLM 0xffffffffu

// ----------------------------- device state -----------------------------
__device__ float g_mem [B_*M_*D_];        // per-batch working rows (filled from regs at t=0)
__device__ float g_qt  [B_*S_*D_];        // (x@Wq+bq)@Wk^T / sqrt(D)
__device__ float g_xg  [B_*S_*D_];        // x@Wg1 + bg
__device__ float g_bgc [D_];              // bv@Wg2
__device__ float g_C   [D_*D_];           // Wv@Wg2
__device__ float g_part[2*B_*GPB*PST];    // partials, double buffered by step parity
__device__ int   g_tidx[2*B_*GPB*8];      // top8 global row ids
__device__ float g_gv  [B_*D_];           // gate vector per batch
__device__ int   g_cnt [2*B_*S_];         // cA[256] then cB[256], zeroed by init

__device__ __forceinline__ int ldacq(const int* p) {
    int v;
    asm volatile("ld.acquire.gpu.global.b32 %0, [%1];" : "=r"(v) : "l"(p) : "memory");
    return v;
}
// release-arrive without the L1D-flushing CCTL.IVALL of __threadfence()
__device__ __forceinline__ void red_release(int* p) {
    asm volatile("red.release.gpu.global.add.s32 [%0], %1;" :: "l"(p), "r"(1) : "memory");
}
__device__ __forceinline__ float dot8(float4 a, float4 b, float4 qa, float4 qb) {
    return a.x*qa.x + a.y*qa.y + a.z*qa.z + a.w*qa.w
         + b.x*qb.x + b.y*qb.y + b.z*qb.z + b.w*qb.w;
}
__device__ __forceinline__ float wredsum(float v) {
    #pragma unroll
    for (int o = 16; o; o >>= 1) v += __shfl_xor_sync(FULLM, v, o);
    return v;
}
__device__ __forceinline__ float wredmax(float v) {
    #pragma unroll
    for (int o = 16; o; o >>= 1) v = fmaxf(v, __shfl_xor_sync(FULLM, v, o));
    return v;
}

// ----------------------------- init kernel (97 blocks) -----------------------------
__global__ void __launch_bounds__(NT)
mal_init(const float* __restrict__ x,  const float* __restrict__ Wq,
         const float* __restrict__ bq, const float* __restrict__ Wk,
         const float* __restrict__ Wv, const float* __restrict__ bv,
         const float* __restrict__ Wg, const float* __restrict__ bg)
{
    __shared__ float s_buf[2048];
    const int bid = blockIdx.x, tid = threadIdx.x;
    const int lane = tid & 31, warp = tid >> 5;

    if (bid == 96) {
        for (int i = tid; i < 2*B_*S_; i += NT) g_cnt[i] = 0;
        float acc = 0.f;
        #pragma unroll 16
        for (int j = 0; j < D_; ++j) acc += bv[j] * Wg[(D_ + j)*D_ + tid];
        g_bgc[tid] = acc;
        return;
    }
    const int which = bid >> 5;               // 0: qt-chain, 1: xg, 2: C
    const int sub   = bid & 31;
    const int r0    = sub * 8;
    const float* srcA = (which == 2) ? (Wv + r0*D_) : (x + r0*D_);
    for (int i = tid; i < 2048; i += NT) s_buf[i] = srcA[i];
    __syncthreads();
    const float* Wcol = (which == 0) ? Wq : (which == 1 ? Wg : (Wg + D_*D_));
    float acc[8];
    #pragma unroll
    for (int r = 0; r < 8; ++r) acc[r] = 0.f;
    #pragma unroll 16
    for (int j = 0; j < D_; ++j) {
        float w = Wcol[j*D_ + tid];
        #pragma unroll
        for (int r = 0; r < 8; ++r) acc[r] += s_buf[r*D_ + j] * w;
    }
    if (which == 1) {
        float bb = bg[tid];
        #pragma unroll
        for (int r = 0; r < 8; ++r) g_xg[(r0+r)*D_ + tid] = acc[r] + bb;
    } else if (which == 2) {
        #pragma unroll
        for (int r = 0; r < 8; ++r) g_C[(r0+r)*D_ + tid] = acc[r];
    } else {
        float bb = bq[tid];
        __syncthreads();
        #pragma unroll
        for (int r = 0; r < 8; ++r) s_buf[r*D_ + tid] = acc[r] + bb;
        __syncthreads();
        float4 t0[8], t1[8];
        #pragma unroll
        for (int r = 0; r < 8; ++r) {
            t0[r] = *(const float4*)(s_buf + r*D_ + lane*4);
            t1[r] = *(const float4*)(s_buf + r*D_ + 128 + lane*4);
        }
        int d = warp * 32;
        float4 w0 = *(const float4*)(Wk + d*D_ + lane*4);
        float4 w1 = *(const float4*)(Wk + d*D_ + 128 + lane*4);
        for (int dd = 0; dd < 32; ++dd) {
            float4 c0 = w0, c1 = w1;
            if (dd < 31) {
                w0 = *(const float4*)(Wk + (d+1)*D_ + lane*4);
                w1 = *(const float4*)(Wk + (d+1)*D_ + 128 + lane*4);
            }
            float dt[8];
            #pragma unroll
            for (int r = 0; r < 8; ++r) {
                dt[r] = t0[r].x*c0.x + t0[r].y*c0.y + t0[r].z*c0.z + t0[r].w*c0.w
                      + t1[r].x*c1.x + t1[r].y*c1.y + t1[r].z*c1.z + t1[r].w*c1.w;
                dt[r] = wredsum(dt[r]);
            }
            if (lane == 0) {
                #pragma unroll
                for (int r = 0; r < 8; ++r) g_qt[(r0+r)*D_ + d] = dt[r] * 0.0625f;
            }
            ++d;
        }
    }
}

// ----------------------------- main persistent kernel -----------------------------
__global__ void __launch_bounds__(NT, 1)
mal_main(const float* __restrict__ x, const float* __restrict__ memory,
         const float* __restrict__ Wv, const float* __restrict__ bv,
         float* __restrict__ out)
{
    __shared__ float s_wacc[8][D_];
    __shared__ float s_wm[8], s_ws[8];
    __shared__ float s_lg[2][128];                 // logits, double buffered by step
    __shared__ unsigned long long s_cand[32];      // top-8-per-warp survivors
    __shared__ int   s_sel[8];
    __shared__ float s_p[D_];
    __shared__ float s_red[NT];

    const int tid  = threadIdx.x, lane = tid & 31, warp = tid >> 5;
    const int bid  = blockIdx.x;
    const int b    = bid >> 4;
    const int blk  = bid & 15;
    int* cA        = g_cnt + b * S_;
    int* cB        = g_cnt + B_*S_ + b * S_;
    const int d0   = lane * 4;
    const int d1   = 128 + lane * 4;
    float* rowp    = g_mem + ((size_t)b*M_ + blk*RPB + warp*16) * D_;

    // ---- prologue: rows copied memory -> g_mem, logits for t=0 ----
    {
        const float4 qa = *(const float4*)(g_qt + (b*S_)*D_ + d0);
        const float4 qb = *(const float4*)(g_qt + (b*S_)*D_ + d1);
        const float* src = memory + (blk*RPB + warp*16) * D_;
        #pragma unroll
        for (int r = 0; r < 16; ++r) {
            float4 fa = *(const float4*)(src + r*D_ + d0);
            float4 fb = *(const float4*)(src + r*D_ + d1);
            *(float4*)(rowp + r*D_ + d0) = fa;
            *(float4*)(rowp + r*D_ + d1) = fb;
            float dt = wredsum(dot8(fa, fb, qa, qb));
            if (lane == 0) s_lg[0][warp*16 + r] = dt;
        }
        __syncwarp();
    }

    for (int t = 0; t < S_; ++t) {
        const int cur = t & 1, nxt = cur ^ 1;
        float* partbase = g_part + cur*(B_*GPB*PST);
        float* part     = partbase + bid * PST;
        int*   tidx     = g_tidx + cur*(B_*GPB*8);

        // ---- 1. owners apply step t-1's gated updates, correct dirty logits ----
        if (t > 0) {
            bool own = false;
            #pragma unroll
            for (int k = 0; k < 8; ++k) own |= ((s_sel[k] >> 7) == blk);
            if (own) {                                   // block-uniform branch
                if (tid == 0) { while (ldacq(&cB[t-1]) < GPB) { } }
                __syncthreads();
                float4 g0 = __ldcg((const float4*)(g_gv + b*D_ + d0));
                float4 g1 = __ldcg((const float4*)(g_gv + b*D_ + d1));
                float4 x0 = __ldg ((const float4*)(x + (size_t)(b*S_ + t-1)*D_ + d0));
                float4 x1 = __ldg ((const float4*)(x + (size_t)(b*S_ + t-1)*D_ + d1));
                const float4 qa = *(const float4*)(g_qt + (b*S_ + t)*D_ + d0);
                const float4 qb = *(const float4*)(g_qt + (b*S_ + t)*D_ + d1);
                #pragma unroll
                for (int k = 0; k < 8; ++k) {
                    int gi = s_sel[k];
                    if ((gi >> 7) == blk && ((gi >> 4) & 7) == warp) {
                        int r = gi & 15;
                        float4 fa = *(float4*)(rowp + r*D_ + d0);
                        float4 fb = *(float4*)(rowp + r*D_ + d1);
                        fa.x += g0.x*(x0.x - fa.x); fa.y += g0.y*(x0.y - fa.y);
                        fa.z += g0.z*(x0.z - fa.z); fa.w += g0.w*(x0.w - fa.w);
                        fb.x += g1.x*(x1.x - fb.x); fb.y += g1.y*(x1.y - fb.y);
                        fb.z += g1.z*(x1.z - fb.z); fb.w += g1.w*(x1.w - fb.w);
                        *(float4*)(rowp + r*D_ + d0) = fa;
                        *(float4*)(rowp + r*D_ + d1) = fb;
                        float dt = wredsum(dot8(fa, fb, qa, qb));
                        if (lane == 0) s_lg[cur][warp*16 + r] = dt;
                    }
                }
                __syncwarp();
            }
        }

        // ---- 2. lane-parallel softmax pieces from smem logits ----
        float lv = (lane < 16) ? s_lg[cur][warp*16 + lane] : NEGINF;
        float mw = wredmax(lv);
        float ev = (lane < 16) ? __expf(lv - mw) : 0.f;
        float sw = wredsum(ev);

        // ---- 3. weighted-sum sweep (FMA only, no reductions) ----
        {
            float4 A = {0,0,0,0}, Bb = {0,0,0,0};
            #pragma unroll
            for (int r = 0; r < 16; ++r) {
                float er = __shfl_sync(FULLM, ev, r);
                float4 fa = *(const float4*)(rowp + r*D_ + d0);
                float4 fb = *(const float4*)(rowp + r*D_ + d1);
                A.x += er*fa.x; A.y += er*fa.y; A.z += er*fa.z; A.w += er*fa.w;
                Bb.x += er*fb.x; Bb.y += er*fb.y; Bb.z += er*fb.z; Bb.w += er*fb.w;
            }
            *(float4*)&s_wacc[warp][d0] = A;
            *(float4*)&s_wacc[warp][d1] = Bb;
            if (lane == 0) { s_wm[warp] = mw; s_ws[warp] = sw; }
        }
        __syncthreads();                                            // S1

        // ---- 4. stage 2: rescaled partial + local top-8 ----
        unsigned long long key1 = 0;
        {
            float m0 = fmaxf(fmaxf(s_wm[0], s_wm[1]), fmaxf(s_wm[2], s_wm[3]));
            float m1 = fmaxf(fmaxf(s_wm[4], s_wm[5]), fmaxf(s_wm[6], s_wm[7]));
            float bm = fmaxf(m0, m1);
            float scv = (lane < 8) ? __expf(s_wm[lane] - bm) : 0.f;
            float pv = 0.f;
            #pragma unroll
            for (int w = 0; w < 8; ++w)
                pv += s_wacc[w][tid] * __shfl_sync(FULLM, scv, w);
            part[2 + tid] = pv;
            if (warp == 0) {
                float t8 = (lane < 8) ? scv * s_ws[lane] : 0.f;
                t8 = wredsum(t8);
                if (lane == 0) { part[0] = bm; part[1] = t8; }
            }
            if (tid < 128) {
                unsigned fb = __float_as_uint(s_lg[cur][tid]);
                fb ^= (fb & 0x80000000u) ? 0xFFFFFFFFu : 0x80000000u;
                key1 = ((unsigned long long)fb << 32) | (unsigned)(~tid);
            }
        }
        if (tid < 128) {
            int rk = 0;
            #pragma unroll
            for (int i = 1; i < 32; ++i) {
                unsigned long long o = __shfl_sync(FULLM, key1, (lane + i) & 31);
                rk += (o > key1);
            }
            if (rk < 8) s_cand[warp*8 + rk] = key1;
        }
        __syncthreads();                                            // S2
        if (warp == 0) {
            unsigned long long k2 = s_cand[lane];
            int rk = 0;
            #pragma unroll
            for (int i = 1; i < 32; ++i) {
                unsigned long long o = __shfl_sync(FULLM, k2, (lane + i) & 31);
                rk += (o > k2);
            }
            if (rk < 8) {
                unsigned fb = (unsigned)(k2 >> 32);
                fb ^= (fb & 0x80000000u) ? 0x80000000u : 0xFFFFFFFFu;
                int c = (int)(~((unsigned)k2)) & 127;
                part[258 + rk] = __uint_as_float(fb);
                tidx[bid*8 + rk] = blk*RPB + c;
            }
        }
        __syncthreads();                                            // S3

        // ---- 5. release barrier A EARLY ----
        if (tid == 0) red_release(&cA[t]);

        // ---- 6. next-step logits (hidden behind barrier propagation) ----
        if (t + 1 < S_) {
            const float4 qa = *(const float4*)(g_qt + (b*S_ + t+1)*D_ + d0);
            const float4 qb = *(const float4*)(g_qt + (b*S_ + t+1)*D_ + d1);
            #pragma unroll
            for (int r = 0; r < 16; ++r) {
                float4 fa = *(const float4*)(rowp + r*D_ + d0);
                float4 fb = *(const float4*)(rowp + r*D_ + d1);
                float dt = wredsum(dot8(fa, fb, qa, qb));
                if (lane == 0) s_lg[nxt][warp*16 + r] = dt;
            }
        }

        // ---- 7. wait barrier A ----
        if (tid == 0) { while (ldacq(&cA[t]) < GPB) { } }
        __syncthreads();                                            // S4

        // ---- 8. merge: lane-parallel scales, shfl-broadcast pv loop ----
        {
            float lv2 = (lane < 16) ? __ldcg(&partbase[(b*GPB + lane)*PST])     : NEGINF;
            float sv2 = (lane < 16) ? __ldcg(&partbase[(b*GPB + lane)*PST + 1]) : 0.f;
            float Mx = wredmax(lv2);
            float scv2 = (lane < 16) ? __expf(lv2 - Mx) : 0.f;
            float Ssum = wredsum(scv2 * sv2);
            float invS = 1.0f / Ssum;
            float pv = 0.f;
            #pragma unroll
            for (int i = 0; i < 16; ++i)
                pv += __ldcg(&partbase[(b*GPB + i)*PST + 2 + tid]) * __shfl_sync(FULLM, scv2, i);
            s_p[tid] = pv * invS;
        }
        // global top-8, stage A (candidates from all 16 blocks)
        if (tid < 128) {
            int i = tid >> 3, j = tid & 7;
            float cv = __ldcg(&partbase[(b*GPB + i)*PST + 258 + j]);
            int   ci = __ldcg(&tidx[(b*GPB + i)*8 + j]);
            unsigned fb = __float_as_uint(cv);
            fb ^= (fb & 0x80000000u) ? 0xFFFFFFFFu : 0x80000000u;
            unsigned long long key2 = ((unsigned long long)fb << 32) | (unsigned)(~ci);
            int rk = 0;
            #pragma unroll
            for (int i2 = 1; i2 < 32; ++i2) {
                unsigned long long o = __shfl_sync(FULLM, key2, (lane + i2) & 31);
                rk += (o > key2);
            }
            if (rk < 8) s_cand[warp*8 + rk] = key2;
        }
        __syncthreads();                                            // S5
        // global top-8, stage B (warp 0) + out/gate slice GEMV (all warps)
        if (warp == 0) {
            unsigned long long k2 = s_cand[lane];
            int rk = 0;
            #pragma unroll
            for (int i = 1; i < 32; ++i) {
                unsigned long long o = __shfl_sync(FULLM, k2, (lane + i) & 31);
                rk += (o > k2);
            }
            if (rk < 8) s_sel[rk] = (int)(~((unsigned)k2));
        }
        {
            const int dbase = blk * 16;
            const float* Mp = (lane < 16) ? (Wv + dbase + lane)
                                          : (g_C + dbase + (lane - 16));
            float acc = 0.f;
            const int k0 = warp * 32;
            #pragma unroll
            for (int kk = 0; kk < 32; ++kk)
                acc += s_p[k0 + kk] * Mp[(k0 + kk)*D_];
            s_red[tid] = acc;
        }
        __syncthreads();                                            // S6
        if (tid < 32) {
            float tot = 0.f;
            #pragma unroll
            for (int w = 0; w < 8; ++w) tot += s_red[w*32 + tid];
            const int dbase = blk * 16;
            if (tid < 16) {
                out[(b*S_ + t)*D_ + dbase + tid] = tot + __ldg(&bv[dbase + tid]);
            } else {
                int d = dbase + tid - 16;
                float z = g_xg[(b*S_ + t)*D_ + d] + g_bgc[d] + tot;
                g_gv[b*D_ + d] = 1.0f / (1.0f + __expf(-z));
            }
        }
        __syncthreads();                                            // S7
        if (tid == 0) red_release(&cB[t]);   // owners wait at t+1
    }
}

// ----------------------------- launch -----------------------------
extern "C" void kernel_launch(void* const* d_in, const int* in_sizes, int n_in,
                              void* d_out, int out_size)
{
    const float* x      = (const float*)d_in[0];
    const float* memory = (const float*)d_in[1];
    const float* Wq     = (const float*)d_in[2];
    const float* bq     = (const float*)d_in[3];
    const float* Wk     = (const float*)d_in[4];
    // d_in[5] = bk : constant logit shift; softmax/top-k invariant -> unused
    const float* Wv     = (const float*)d_in[6];
    const float* bv     = (const float*)d_in[7];
    const float* Wg     = (const float*)d_in[8];
    const float* bg     = (const float*)d_in[9];
    float* out = (float*)d_out;

    mal_init<<<97, NT>>>(x, Wq, bq, Wk, Wv, bv, Wg, bg);
    mal_main<<<NBLK, NT>>>(x, memory, Wv, bv, out);
}